// round 3
// baseline (speedup 1.0000x reference)
#include <cuda_runtime.h>

// Problem constants (fixed by the dataset)
#define BB    8
#define HH    112
#define WW_   112
#define CC    128
#define NHH   4
#define WSS   7
#define SSS   3
#define NN    49            // tokens per window
#define NP    52            // padded token stride (mult of 4 -> float4 aligned)
#define HD    32            // head dim
#define NWIN  256           // windows per image (16x16)
#define BWTOT 2048          // total windows = BB*NWIN
#define MROWS 100352        // BWTOT*NN
#define QK_SCALE 0.17677669529663687f   // 1/sqrt(32)

// Scratch (static __device__ — no allocations allowed)
// g_qkv layout: [which(3)][bw(2048)][h(4)][tok(49)][d(32)]
__device__ float g_qkv[(size_t)3 * BWTOT * NHH * NN * HD];
// g_att layout: [row(100352)][c(128)]  (window-major rows)
__device__ float g_att[(size_t)MROWS * CC];

// Shared-memory stride for the transposed GEMM tiles: multiple of 4 (float4-
// aligned compute loads) and bank-decorrelated for the transposed stores.
#define SSTRIDE 132

// ---------------------------------------------------------------------------
// Kernel 1: QKV GEMM with fused shift-roll + window-partition gather.
// out[r, o] = sum_c xw[r, c] * qkv_w[o, c] + qkv_b[o]
// M = 100352 (128 rows/block), N = 384 (128 cols/block), K = 128.
// ---------------------------------------------------------------------------
__global__ __launch_bounds__(256) void qkv_gemm(const float* __restrict__ x,
                                                const float* __restrict__ w,
                                                const float* __restrict__ b) {
    const int rowBase = blockIdx.x * 128;
    const int colBase = blockIdx.y * 128;
    __shared__ float sA[16 * SSTRIDE];   // [kk][row]
    __shared__ float sB[16 * SSTRIDE];   // [kk][col]
    __shared__ int   sRow[128];          // gather base offset into x per tile row

    const int tid = threadIdx.x;
    if (tid < 128) {
        int rgl = rowBase + tid;
        int bw  = rgl / NN, tok = rgl % NN;
        int bimg = bw >> 8;                 // /256
        int wi = (bw >> 4) & 15, wj = bw & 15;
        int i0 = tok / WSS, j0 = tok % WSS;
        int sh = (wi * WSS + i0 + SSS) % HH;    // roll(-ss) gather
        int sw = (wj * WSS + j0 + SSS) % WW_;
        sRow[tid] = ((bimg * (HH * WW_)) + sh * WW_ + sw) * CC;
    }
    __syncthreads();

    float acc[8][8] = {};
    const int ty = tid >> 4, tx = tid & 15;   // 16 x 16 thread grid

    for (int k0 = 0; k0 < CC; k0 += 16) {
        #pragma unroll
        for (int q = 0; q < 2; q++) {
            int i = tid + q * 256;            // 0..511
            int r = i >> 2, c4 = i & 3;       // row, which float4 along k
            float4 v = *(const float4*)(x + sRow[r] + k0 + c4 * 4);
            sA[(c4 * 4 + 0) * SSTRIDE + r] = v.x;
            sA[(c4 * 4 + 1) * SSTRIDE + r] = v.y;
            sA[(c4 * 4 + 2) * SSTRIDE + r] = v.z;
            sA[(c4 * 4 + 3) * SSTRIDE + r] = v.w;
        }
        #pragma unroll
        for (int q = 0; q < 2; q++) {
            int i = tid + q * 256;
            int o = i >> 2, c4 = i & 3;
            float4 v = *(const float4*)(w + (size_t)(colBase + o) * CC + k0 + c4 * 4);
            sB[(c4 * 4 + 0) * SSTRIDE + o] = v.x;
            sB[(c4 * 4 + 1) * SSTRIDE + o] = v.y;
            sB[(c4 * 4 + 2) * SSTRIDE + o] = v.z;
            sB[(c4 * 4 + 3) * SSTRIDE + o] = v.w;
        }
        __syncthreads();
        #pragma unroll
        for (int kk = 0; kk < 16; kk++) {
            float a[8], bb[8];
            *(float4*)(a)      = *(const float4*)(sA + kk * SSTRIDE + ty * 8);
            *(float4*)(a + 4)  = *(const float4*)(sA + kk * SSTRIDE + ty * 8 + 4);
            *(float4*)(bb)     = *(const float4*)(sB + kk * SSTRIDE + tx * 8);
            *(float4*)(bb + 4) = *(const float4*)(sB + kk * SSTRIDE + tx * 8 + 4);
            #pragma unroll
            for (int ii = 0; ii < 8; ii++)
                #pragma unroll
                for (int jj = 0; jj < 8; jj++)
                    acc[ii][jj] += a[ii] * bb[jj];
        }
        __syncthreads();
    }

    // Epilogue: scatter into g_qkv[which][bw][h][tok][d].
    const int oB = colBase + tx * 8;
    const int which = oB >> 7;
    const int rem = oB & 127;
    const int h = rem >> 5, d0 = rem & 31;
    #pragma unroll
    for (int ii = 0; ii < 8; ii++) {
        int rgl = rowBase + ty * 8 + ii;
        int bw  = rgl / NN, tok = rgl % NN;
        size_t dst = ((((size_t)which * BWTOT + bw) * NHH + h) * NN + tok) * HD + d0;
        float4 v0, v1;
        v0.x = acc[ii][0] + b[oB + 0];  v0.y = acc[ii][1] + b[oB + 1];
        v0.z = acc[ii][2] + b[oB + 2];  v0.w = acc[ii][3] + b[oB + 3];
        v1.x = acc[ii][4] + b[oB + 4];  v1.y = acc[ii][5] + b[oB + 5];
        v1.z = acc[ii][6] + b[oB + 6];  v1.w = acc[ii][7] + b[oB + 7];
        *(float4*)(g_qkv + dst)     = v0;
        *(float4*)(g_qkv + dst + 4) = v1;
    }
}

// ---------------------------------------------------------------------------
// Kernel 2: per-(window, head) attention. Grid = 8192 blocks of 256 threads.
// Vectorized: scores 4-kj per thread (float4 on padded skT), PV 4-d per thread.
// ---------------------------------------------------------------------------
__global__ __launch_bounds__(256) void attn_kernel(const float* __restrict__ mask,
                                                   const float* __restrict__ rpb,
                                                   const int*   __restrict__ rel) {
    const int bh = blockIdx.x;       // bw*4 + h
    const int bw = bh >> 2, h = bh & 3;
    const int wm = bw & 255;         // window index within image for mask

    __shared__ float sq[NN * HD];    // [tok][d]
    __shared__ float skT[HD * NP];   // [d][tok]  padded stride 52
    __shared__ float sv[NN * HD];    // [tok][d]
    __shared__ float sp[NN * NP];    // scores / probs, padded stride 52

    const int tid = threadIdx.x;
    const float* qb = g_qkv + (size_t)bh * (NN * HD);
    const float* kb = g_qkv + (size_t)(BWTOT * NHH + bh) * (NN * HD);
    const float* vb = g_qkv + (size_t)(2 * BWTOT * NHH + bh) * (NN * HD);

    for (int i = tid; i < NN * HD; i += 256) {
        int tok = i >> 5, d = i & 31;
        sq[i] = qb[i] * QK_SCALE;
        skT[d * NP + tok] = kb[i];
        sv[i] = vb[i];
    }
    __syncthreads();

    // scores + bias + mask: each work item = (qi, kj0..kj0+3). 49 qi x 13 groups.
    for (int wi_ = tid; wi_ < NN * 13; wi_ += 256) {
        int qi = wi_ / 13, g = wi_ % 13;
        int kj0 = g * 4;
        float4 s = make_float4(0.f, 0.f, 0.f, 0.f);
        #pragma unroll
        for (int d4 = 0; d4 < 8; d4++) {
            float4 qv = *(const float4*)(sq + qi * HD + d4 * 4);
            float4 k0 = *(const float4*)(skT + (d4 * 4 + 0) * NP + kj0);
            float4 k1 = *(const float4*)(skT + (d4 * 4 + 1) * NP + kj0);
            float4 k2 = *(const float4*)(skT + (d4 * 4 + 2) * NP + kj0);
            float4 k3 = *(const float4*)(skT + (d4 * 4 + 3) * NP + kj0);
            s.x += qv.x * k0.x + qv.y * k1.x + qv.z * k2.x + qv.w * k3.x;
            s.y += qv.x * k0.y + qv.y * k1.y + qv.z * k2.y + qv.w * k3.y;
            s.z += qv.x * k0.z + qv.y * k1.z + qv.z * k2.z + qv.w * k3.z;
            s.w += qv.x * k0.w + qv.y * k1.w + qv.z * k2.w + qv.w * k3.w;
        }
        // add bias + mask (guard tail: kj 49..51 invalid)
        const float* mrow = mask + (size_t)wm * (NN * NN) + qi * NN;
        const int*   rrow = rel + qi * NN;
        float out[4] = {s.x, s.y, s.z, s.w};
        #pragma unroll
        for (int u = 0; u < 4; u++) {
            int kj = kj0 + u;
            if (kj < NN)
                sp[qi * NP + kj] = out[u] + rpb[rrow[kj] * NHH + h] + mrow[kj];
        }
    }
    __syncthreads();

    // row softmax (one thread per query row)
    if (tid < NN) {
        float m = -1e30f;
        #pragma unroll 7
        for (int j = 0; j < NN; j++) m = fmaxf(m, sp[tid * NP + j]);
        float sum = 0.f;
        #pragma unroll 7
        for (int j = 0; j < NN; j++) {
            float e = __expf(sp[tid * NP + j] - m);
            sp[tid * NP + j] = e;
            sum += e;
        }
        float inv = 1.0f / sum;
        #pragma unroll 7
        for (int j = 0; j < NN; j++) sp[tid * NP + j] *= inv;
    }
    __syncthreads();

    // out = P @ V : each work item = (qi, d4). 49 * 8 = 392 items.
    for (int wi_ = tid; wi_ < NN * 8; wi_ += 256) {
        int qi = wi_ >> 3, d4 = wi_ & 7;
        float4 o = make_float4(0.f, 0.f, 0.f, 0.f);
        #pragma unroll 7
        for (int j = 0; j < NN; j++) {
            float p = sp[qi * NP + j];
            float4 vv = *(const float4*)(sv + j * HD + d4 * 4);
            o.x += p * vv.x; o.y += p * vv.y; o.z += p * vv.z; o.w += p * vv.w;
        }
        *(float4*)(g_att + ((size_t)(bw * NN + qi)) * CC + h * HD + d4 * 4) = o;
    }
}

// ---------------------------------------------------------------------------
// Kernel 3: projection GEMM + fused window-reverse + reverse-roll scatter.
// out[r, o] = sum_c g_att[r, c] * proj_w[o, c] + proj_b[o]
// M = 100352 (128/block), N = 128 (one col block), K = 128.
// ---------------------------------------------------------------------------
__global__ __launch_bounds__(256) void proj_gemm(const float* __restrict__ w,
                                                 const float* __restrict__ b,
                                                 float* __restrict__ out) {
    const int rowBase = blockIdx.x * 128;
    __shared__ float sA[16 * SSTRIDE];
    __shared__ float sB[16 * SSTRIDE];
    __shared__ int   sOut[128];     // scatter base offset into out per tile row

    const int tid = threadIdx.x;
    if (tid < 128) {
        int rgl = rowBase + tid;
        int bw  = rgl / NN, tok = rgl % NN;
        int bimg = bw >> 8;
        int wi = (bw >> 4) & 15, wj = bw & 15;
        int i0 = tok / WSS, j0 = tok % WSS;
        int dh = (wi * WSS + i0 + SSS) % HH;    // roll(+ss) scatter target
        int dw = (wj * WSS + j0 + SSS) % WW_;
        sOut[tid] = ((bimg * (HH * WW_)) + dh * WW_ + dw) * CC;
    }
    __syncthreads();

    float acc[8][8] = {};
    const int ty = tid >> 4, tx = tid & 15;

    for (int k0 = 0; k0 < CC; k0 += 16) {
        #pragma unroll
        for (int q = 0; q < 2; q++) {
            int i = tid + q * 256;
            int r = i >> 2, c4 = i & 3;
            float4 v = *(const float4*)(g_att + (size_t)(rowBase + r) * CC + k0 + c4 * 4);
            sA[(c4 * 4 + 0) * SSTRIDE + r] = v.x;
            sA[(c4 * 4 + 1) * SSTRIDE + r] = v.y;
            sA[(c4 * 4 + 2) * SSTRIDE + r] = v.z;
            sA[(c4 * 4 + 3) * SSTRIDE + r] = v.w;
        }
        #pragma unroll
        for (int q = 0; q < 2; q++) {
            int i = tid + q * 256;
            int o = i >> 2, c4 = i & 3;
            float4 v = *(const float4*)(w + (size_t)o * CC + k0 + c4 * 4);
            sB[(c4 * 4 + 0) * SSTRIDE + o] = v.x;
            sB[(c4 * 4 + 1) * SSTRIDE + o] = v.y;
            sB[(c4 * 4 + 2) * SSTRIDE + o] = v.z;
            sB[(c4 * 4 + 3) * SSTRIDE + o] = v.w;
        }
        __syncthreads();
        #pragma unroll
        for (int kk = 0; kk < 16; kk++) {
            float a[8], bb[8];
            *(float4*)(a)      = *(const float4*)(sA + kk * SSTRIDE + ty * 8);
            *(float4*)(a + 4)  = *(const float4*)(sA + kk * SSTRIDE + ty * 8 + 4);
            *(float4*)(bb)     = *(const float4*)(sB + kk * SSTRIDE + tx * 8);
            *(float4*)(bb + 4) = *(const float4*)(sB + kk * SSTRIDE + tx * 8 + 4);
            #pragma unroll
            for (int ii = 0; ii < 8; ii++)
                #pragma unroll
                for (int jj = 0; jj < 8; jj++)
                    acc[ii][jj] += a[ii] * bb[jj];
        }
        __syncthreads();
    }

    const int oB = tx * 8;
    #pragma unroll
    for (int ii = 0; ii < 8; ii++) {
        int r = ty * 8 + ii;
        float4 v0, v1;
        v0.x = acc[ii][0] + b[oB + 0];  v0.y = acc[ii][1] + b[oB + 1];
        v0.z = acc[ii][2] + b[oB + 2];  v0.w = acc[ii][3] + b[oB + 3];
        v1.x = acc[ii][4] + b[oB + 4];  v1.y = acc[ii][5] + b[oB + 5];
        v1.z = acc[ii][6] + b[oB + 6];  v1.w = acc[ii][7] + b[oB + 7];
        *(float4*)(out + sOut[r] + oB)     = v0;
        *(float4*)(out + sOut[r] + oB + 4) = v1;
    }
}

// ---------------------------------------------------------------------------
// Launch
// inputs: 0 x, 1 mask_matrix, 2 qkv_w, 3 qkv_b, 4 proj_w, 5 proj_b,
//         6 rpb_table, 7 rel_index (int32), 8.. scalars (ignored, hardcoded)
// ---------------------------------------------------------------------------
extern "C" void kernel_launch(void* const* d_in, const int* in_sizes, int n_in,
                              void* d_out, int out_size) {
    const float* x      = (const float*)d_in[0];
    const float* mask   = (const float*)d_in[1];
    const float* qkv_w  = (const float*)d_in[2];
    const float* qkv_b  = (const float*)d_in[3];
    const float* proj_w = (const float*)d_in[4];
    const float* proj_b = (const float*)d_in[5];
    const float* rpb    = (const float*)d_in[6];
    const int*   rel    = (const int*)d_in[7];
    float* out = (float*)d_out;

    dim3 g1(MROWS / 128, 384 / 128);     // (784, 3)
    qkv_gemm<<<g1, 256>>>(x, qkv_w, qkv_b);

    attn_kernel<<<BWTOT * NHH, 256>>>(mask, rpb, rel);

    dim3 g3(MROWS / 128, 1);             // (784, 1)
    proj_gemm<<<g3, 256>>>(proj_w, proj_b, out);
}

// round 5
// speedup vs baseline: 1.5547x; 1.5547x over previous
#include <cuda_runtime.h>
#include <cstdint>

// Problem constants (fixed by the dataset)
#define BB    8
#define HH    112
#define WW_   112
#define CC    128
#define NHH   4
#define WSS   7
#define SSS   3
#define NN    49            // tokens per window
#define NP    52            // padded token stride (mult of 4 -> float4 aligned)
#define HD    32            // head dim
#define NWIN  256           // windows per image (16x16)
#define BWTOT 2048          // total windows = BB*NWIN
#define MROWS 100352        // BWTOT*NN
#define QK_SCALE 0.17677669529663687f   // 1/sqrt(32)

// Scratch (static __device__ — no allocations allowed)
// g_qkv layout: [which(3)][bw(2048)][h(4)][tok(49)][d(32)]
__device__ float g_qkv[(size_t)3 * BWTOT * NHH * NN * HD];
// g_att layout: [row(100352)][c(128)]  (window-major rows)
__device__ float g_att[(size_t)MROWS * CC];
// g_bias layout: [wm(256)][h(4)][qi(49)][kj padded to 52]  (rpb gather + mask)
__device__ float g_bias[(size_t)NWIN * NHH * NN * NP];

// tf32 helpers --------------------------------------------------------------
__device__ __forceinline__ unsigned f2tf(float f) {
    unsigned u;
    asm("cvt.rna.tf32.f32 %0, %1;" : "=r"(u) : "f"(f));
    return u;
}

// D += A(16x8) * B(8x8), tf32 inputs, f32 accum.
#define MMA8(d, a, b)                                                          \
    asm("mma.sync.aligned.m16n8k8.row.col.f32.tf32.tf32.f32 "                  \
        "{%0,%1,%2,%3},{%4,%5,%6,%7},{%8,%9},{%0,%1,%2,%3};"                   \
        : "+f"((d)[0]), "+f"((d)[1]), "+f"((d)[2]), "+f"((d)[3])               \
        : "r"((a)[0]), "r"((a)[1]), "r"((a)[2]), "r"((a)[3]),                  \
          "r"((b)[0]), "r"((b)[1]))

// smem tile: [k(32)][row(128)] transposed, stride 136 (== 8 mod 32), rows
// XOR-swizzled by ((k>>2)&3)<<3 -> conflict-free stores AND fragment loads.
#define ASTR 136

// ---------------------------------------------------------------------------
// Kernel 0: precompute combined bias table.
// combined[wm][h][qi][kj] = rpb[rel[qi*49+kj]*4 + h] + mask[wm][qi][kj]
// ---------------------------------------------------------------------------
__global__ __launch_bounds__(256) void bias_precompute(const float* __restrict__ mask,
                                                       const float* __restrict__ rpb,
                                                       const int*   __restrict__ rel) {
    int idx = blockIdx.x * 256 + threadIdx.x;     // over 256*4*49*49
    if (idx >= NWIN * NHH * NN * NN) return;
    int kj = idx % NN;
    int t  = idx / NN;
    int qi = t % NN;
    t /= NN;
    int h  = t % NHH;
    int wm = t / NHH;
    float v = rpb[rel[qi * NN + kj] * NHH + h] + mask[(size_t)wm * (NN * NN) + qi * NN + kj];
    g_bias[(((size_t)wm * NHH + h) * NN + qi) * NP + kj] = v;
}

// ---------------------------------------------------------------------------
// Kernel 1: QKV GEMM (tf32 MMA) with fused shift-roll + window gather.
// out[r, o] = sum_c xw[r, c] * qkv_w[o, c] + qkv_b[o]
// Block tile 128(M) x 128(N), K=128 in 4 chunks of 32. 8 warps: 2(M) x 4(N),
// warp tile 64x32 = 4x4 of m16n8k8.
// ---------------------------------------------------------------------------
__global__ __launch_bounds__(256, 2) void qkv_gemm(const float* __restrict__ x,
                                                   const float* __restrict__ w,
                                                   const float* __restrict__ b) {
    const int rowBase = blockIdx.x * 128;
    const int colBase = blockIdx.y * 128;
    __shared__ unsigned sA[32 * ASTR];
    __shared__ unsigned sB[32 * ASTR];
    __shared__ int sRow[128];

    const int tid = threadIdx.x;
    if (tid < 128) {
        int rgl = rowBase + tid;
        int bw  = rgl / NN, tok = rgl % NN;
        int bimg = bw >> 8;
        int wi = (bw >> 4) & 15, wj = bw & 15;
        int i0 = tok / WSS, j0 = tok % WSS;
        int sh = (wi * WSS + i0 + SSS) % HH;    // roll(-ss) gather
        int sw = (wj * WSS + j0 + SSS) % WW_;
        sRow[tid] = ((bimg * (HH * WW_)) + sh * WW_ + sw) * CC;
    }
    __syncthreads();

    const int lane = tid & 31;
    const int wid  = tid >> 5;
    const int warpM = (wid >> 2) * 64;
    const int warpN = (wid & 3) * 32;
    const int fc = lane & 3, fr = lane >> 2;   // fragment col(k) / row groups

    float d[4][4][4];
    #pragma unroll
    for (int i = 0; i < 4; i++)
        #pragma unroll
        for (int j = 0; j < 4; j++)
            #pragma unroll
            for (int e = 0; e < 4; e++) d[i][j][e] = 0.f;

    const int lc2 = tid & 3;            // float4 index within 16-k half
    const int lr0 = tid >> 2;           // 0..63

    for (int k0 = 0; k0 < CC; k0 += 32) {
        // ---- A tile: 128 rows x 32 k ----
        float4 va[4];
        #pragma unroll
        for (int q = 0; q < 4; q++) {
            int r  = lr0 + 64 * (q & 1);
            int kh = q >> 1;
            va[q] = *(const float4*)(x + sRow[r] + k0 + kh * 16 + lc2 * 4);
        }
        #pragma unroll
        for (int q = 0; q < 4; q++) {
            int r  = lr0 + 64 * (q & 1);
            int kh = q >> 1;
            const float* pv = (const float*)&va[q];
            #pragma unroll
            for (int e = 0; e < 4; e++) {
                int k = kh * 16 + lc2 * 4 + e;
                sA[k * ASTR + (r ^ (lc2 << 3))] = f2tf(pv[e]);
            }
        }
        // ---- B tile: 128 cols x 32 k ----
        float4 vb[4];
        #pragma unroll
        for (int q = 0; q < 4; q++) {
            int o  = lr0 + 64 * (q & 1);
            int kh = q >> 1;
            vb[q] = *(const float4*)(w + (size_t)(colBase + o) * CC + k0 + kh * 16 + lc2 * 4);
        }
        #pragma unroll
        for (int q = 0; q < 4; q++) {
            int o  = lr0 + 64 * (q & 1);
            int kh = q >> 1;
            const float* pv = (const float*)&vb[q];
            #pragma unroll
            for (int e = 0; e < 4; e++) {
                int k = kh * 16 + lc2 * 4 + e;
                sB[k * ASTR + (o ^ (lc2 << 3))] = f2tf(pv[e]);
            }
        }
        __syncthreads();

        #pragma unroll
        for (int ks = 0; ks < 4; ks++) {
            const int kA = ks * 8 + fc;
            const int kB = kA + 4;
            const int swLo = ((2 * ks) & 3) << 3;
            const int swHi = ((2 * ks + 1) & 3) << 3;
            unsigned af[4][4], bf[4][2];
            #pragma unroll
            for (int mt = 0; mt < 4; mt++) {
                int row = warpM + mt * 16 + fr;
                af[mt][0] = sA[kA * ASTR + (row ^ swLo)];
                af[mt][1] = sA[kA * ASTR + ((row + 8) ^ swLo)];
                af[mt][2] = sA[kB * ASTR + (row ^ swHi)];
                af[mt][3] = sA[kB * ASTR + ((row + 8) ^ swHi)];
            }
            #pragma unroll
            for (int nt = 0; nt < 4; nt++) {
                int col = warpN + nt * 8 + fr;
                bf[nt][0] = sB[kA * ASTR + (col ^ swLo)];
                bf[nt][1] = sB[kB * ASTR + (col ^ swHi)];
            }
            #pragma unroll
            for (int mt = 0; mt < 4; mt++)
                #pragma unroll
                for (int nt = 0; nt < 4; nt++)
                    MMA8(d[mt][nt], af[mt], bf[nt]);
        }
        __syncthreads();
    }

    // Epilogue: scatter into g_qkv[which][bw][h][tok][d]
    const int c2e = (lane & 3) * 2;
    #pragma unroll
    for (int mt = 0; mt < 4; mt++) {
        #pragma unroll
        for (int half = 0; half < 2; half++) {
            int rgl = rowBase + warpM + mt * 16 + fr + half * 8;
            int bw  = rgl / NN, tok = rgl % NN;
            #pragma unroll
            for (int nt = 0; nt < 4; nt++) {
                int o = colBase + warpN + nt * 8 + c2e;
                int which = o >> 7;
                int rem = o & 127;
                int h = rem >> 5, d0i = rem & 31;
                size_t dst = ((((size_t)which * BWTOT + bw) * NHH + h) * NN + tok) * HD + d0i;
                float2 v;
                v.x = d[mt][nt][half * 2 + 0] + b[o];
                v.y = d[mt][nt][half * 2 + 1] + b[o + 1];
                *(float2*)(g_qkv + dst) = v;
            }
        }
    }
}

// ---------------------------------------------------------------------------
// Kernel 2: per-(window, head) attention. Grid = 8192 blocks of 256 threads.
// Vectorized scores/PV, precomputed bias table, 4-threads-per-row softmax.
// ---------------------------------------------------------------------------
__global__ __launch_bounds__(256) void attn_kernel() {
    const int bh = blockIdx.x;       // bw*4 + h
    const int bw = bh >> 2, h = bh & 3;
    const int wm = bw & 255;

    __shared__ __align__(16) float sq[NN * HD];
    __shared__ __align__(16) float skT[HD * NP];
    __shared__ __align__(16) float sv[NN * HD];
    __shared__ __align__(16) float sp[NN * NP];

    const int tid = threadIdx.x;
    const float* qb = g_qkv + (size_t)bh * (NN * HD);
    const float* kb = g_qkv + (size_t)(BWTOT * NHH + bh) * (NN * HD);
    const float* vb = g_qkv + (size_t)(2 * BWTOT * NHH + bh) * (NN * HD);
    const float* cb = g_bias + ((size_t)wm * NHH + h) * (NN * NP);

    for (int i = tid; i < NN * HD; i += 256) {
        int tok = i >> 5, d = i & 31;
        sq[i] = qb[i] * QK_SCALE;
        skT[d * NP + tok] = kb[i];
        sv[i] = vb[i];
    }
    __syncthreads();

    // scores + combined (bias+mask): one float4 load per 4 kj.
    for (int wi_ = tid; wi_ < NN * 13; wi_ += 256) {
        int qi = wi_ / 13, g = wi_ % 13;
        int kj0 = g * 4;
        float4 add4 = *(const float4*)(cb + qi * NP + kj0);
        float4 s = add4;
        #pragma unroll
        for (int d4 = 0; d4 < 8; d4++) {
            float4 qv = *(const float4*)(sq + qi * HD + d4 * 4);
            float4 k0 = *(const float4*)(skT + (d4 * 4 + 0) * NP + kj0);
            float4 k1 = *(const float4*)(skT + (d4 * 4 + 1) * NP + kj0);
            float4 k2 = *(const float4*)(skT + (d4 * 4 + 2) * NP + kj0);
            float4 k3 = *(const float4*)(skT + (d4 * 4 + 3) * NP + kj0);
            s.x += qv.x * k0.x + qv.y * k1.x + qv.z * k2.x + qv.w * k3.x;
            s.y += qv.x * k0.y + qv.y * k1.y + qv.z * k2.y + qv.w * k3.y;
            s.z += qv.x * k0.z + qv.y * k1.z + qv.z * k2.z + qv.w * k3.z;
            s.w += qv.x * k0.w + qv.y * k1.w + qv.z * k2.w + qv.w * k3.w;
        }
        *(float4*)(sp + qi * NP + kj0) = s;   // tail kj 49..51 written but ignored
    }
    __syncthreads();

    // softmax: 4 threads per row, shfl reductions within the quad.
    {
        int row = tid >> 2;
        int l4  = tid & 3;
        int rr  = row < NN ? row : NN - 1;
        float m = -1e30f;
        for (int j = l4; j < NN; j += 4) m = fmaxf(m, sp[rr * NP + j]);
        m = fmaxf(m, __shfl_xor_sync(0xffffffffu, m, 1));
        m = fmaxf(m, __shfl_xor_sync(0xffffffffu, m, 2));
        float ev[13];
        float sum = 0.f;
        int cnt = 0;
        for (int j = l4; j < NN; j += 4) {
            float e = __expf(sp[rr * NP + j] - m);
            ev[cnt++] = e;
            sum += e;
        }
        sum += __shfl_xor_sync(0xffffffffu, sum, 1);
        sum += __shfl_xor_sync(0xffffffffu, sum, 2);
        float inv = 1.0f / sum;
        if (row < NN) {
            cnt = 0;
            for (int j = l4; j < NN; j += 4) sp[row * NP + j] = ev[cnt++] * inv;
        }
    }
    __syncthreads();

    // out = P @ V
    for (int wi_ = tid; wi_ < NN * 8; wi_ += 256) {
        int qi = wi_ >> 3, d4 = wi_ & 7;
        float4 o = make_float4(0.f, 0.f, 0.f, 0.f);
        #pragma unroll 7
        for (int j = 0; j < NN; j++) {
            float p = sp[qi * NP + j];
            float4 vv = *(const float4*)(sv + j * HD + d4 * 4);
            o.x += p * vv.x; o.y += p * vv.y; o.z += p * vv.z; o.w += p * vv.w;
        }
        *(float4*)(g_att + ((size_t)(bw * NN + qi)) * CC + h * HD + d4 * 4) = o;
    }
}

// ---------------------------------------------------------------------------
// Kernel 3: projection GEMM (tf32 MMA) + fused window-reverse scatter.
// Block tile 128(M) x 128(N=CC), K=128.
// ---------------------------------------------------------------------------
__global__ __launch_bounds__(256, 2) void proj_gemm(const float* __restrict__ w,
                                                    const float* __restrict__ b,
                                                    float* __restrict__ out) {
    const int rowBase = blockIdx.x * 128;
    __shared__ unsigned sA[32 * ASTR];
    __shared__ unsigned sB[32 * ASTR];
    __shared__ int sOut[128];

    const int tid = threadIdx.x;
    if (tid < 128) {
        int rgl = rowBase + tid;
        int bw  = rgl / NN, tok = rgl % NN;
        int bimg = bw >> 8;
        int wi = (bw >> 4) & 15, wj = bw & 15;
        int i0 = tok / WSS, j0 = tok % WSS;
        int dh = (wi * WSS + i0 + SSS) % HH;    // roll(+ss) scatter target
        int dw = (wj * WSS + j0 + SSS) % WW_;
        sOut[tid] = ((bimg * (HH * WW_)) + dh * WW_ + dw) * CC;
    }
    __syncthreads();

    const int lane = tid & 31;
    const int wid  = tid >> 5;
    const int warpM = (wid >> 2) * 64;
    const int warpN = (wid & 3) * 32;
    const int fc = lane & 3, fr = lane >> 2;

    float d[4][4][4];
    #pragma unroll
    for (int i = 0; i < 4; i++)
        #pragma unroll
        for (int j = 0; j < 4; j++)
            #pragma unroll
            for (int e = 0; e < 4; e++) d[i][j][e] = 0.f;

    const int lc2 = tid & 3;
    const int lr0 = tid >> 2;

    for (int k0 = 0; k0 < CC; k0 += 32) {
        float4 va[4];
        #pragma unroll
        for (int q = 0; q < 4; q++) {
            int r  = lr0 + 64 * (q & 1);
            int kh = q >> 1;
            va[q] = *(const float4*)(g_att + (size_t)(rowBase + r) * CC + k0 + kh * 16 + lc2 * 4);
        }
        #pragma unroll
        for (int q = 0; q < 4; q++) {
            int r  = lr0 + 64 * (q & 1);
            int kh = q >> 1;
            const float* pv = (const float*)&va[q];
            #pragma unroll
            for (int e = 0; e < 4; e++) {
                int k = kh * 16 + lc2 * 4 + e;
                sA[k * ASTR + (r ^ (lc2 << 3))] = f2tf(pv[e]);
            }
        }
        float4 vb[4];
        #pragma unroll
        for (int q = 0; q < 4; q++) {
            int o  = lr0 + 64 * (q & 1);
            int kh = q >> 1;
            vb[q] = *(const float4*)(w + (size_t)o * CC + k0 + kh * 16 + lc2 * 4);
        }
        #pragma unroll
        for (int q = 0; q < 4; q++) {
            int o  = lr0 + 64 * (q & 1);
            int kh = q >> 1;
            const float* pv = (const float*)&vb[q];
            #pragma unroll
            for (int e = 0; e < 4; e++) {
                int k = kh * 16 + lc2 * 4 + e;
                sB[k * ASTR + (o ^ (lc2 << 3))] = f2tf(pv[e]);
            }
        }
        __syncthreads();

        #pragma unroll
        for (int ks = 0; ks < 4; ks++) {
            const int kA = ks * 8 + fc;
            const int kB = kA + 4;
            const int swLo = ((2 * ks) & 3) << 3;
            const int swHi = ((2 * ks + 1) & 3) << 3;
            unsigned af[4][4], bf[4][2];
            #pragma unroll
            for (int mt = 0; mt < 4; mt++) {
                int row = warpM + mt * 16 + fr;
                af[mt][0] = sA[kA * ASTR + (row ^ swLo)];
                af[mt][1] = sA[kA * ASTR + ((row + 8) ^ swLo)];
                af[mt][2] = sA[kB * ASTR + (row ^ swHi)];
                af[mt][3] = sA[kB * ASTR + ((row + 8) ^ swHi)];
            }
            #pragma unroll
            for (int nt = 0; nt < 4; nt++) {
                int col = warpN + nt * 8 + fr;
                bf[nt][0] = sB[kA * ASTR + (col ^ swLo)];
                bf[nt][1] = sB[kB * ASTR + (col ^ swHi)];
            }
            #pragma unroll
            for (int mt = 0; mt < 4; mt++)
                #pragma unroll
                for (int nt = 0; nt < 4; nt++)
                    MMA8(d[mt][nt], af[mt], bf[nt]);
        }
        __syncthreads();
    }

    const int c2e = (lane & 3) * 2;
    #pragma unroll
    for (int mt = 0; mt < 4; mt++) {
        #pragma unroll
        for (int half = 0; half < 2; half++) {
            int lr = warpM + mt * 16 + fr + half * 8;
            #pragma unroll
            for (int nt = 0; nt < 4; nt++) {
                int o = warpN + nt * 8 + c2e;
                float2 v;
                v.x = d[mt][nt][half * 2 + 0] + b[o];
                v.y = d[mt][nt][half * 2 + 1] + b[o + 1];
                *(float2*)(out + sOut[lr] + o) = v;
            }
        }
    }
}

// ---------------------------------------------------------------------------
// Launch
// ---------------------------------------------------------------------------
extern "C" void kernel_launch(void* const* d_in, const int* in_sizes, int n_in,
                              void* d_out, int out_size) {
    const float* x      = (const float*)d_in[0];
    const float* mask   = (const float*)d_in[1];
    const float* qkv_w  = (const float*)d_in[2];
    const float* qkv_b  = (const float*)d_in[3];
    const float* proj_w = (const float*)d_in[4];
    const float* proj_b = (const float*)d_in[5];
    const float* rpb    = (const float*)d_in[6];
    const int*   rel    = (const int*)d_in[7];
    float* out = (float*)d_out;

    int nbias = NWIN * NHH * NN * NN;
    bias_precompute<<<(nbias + 255) / 256, 256>>>(mask, rpb, rel);

    dim3 g1(MROWS / 128, 384 / 128);     // (784, 3)
    qkv_gemm<<<g1, 256>>>(x, qkv_w, qkv_b);

    attn_kernel<<<BWTOT * NHH, 256>>>();

    dim3 g3(MROWS / 128, 1);             // (784, 1)
    proj_gemm<<<g3, 256>>>(proj_w, proj_b, out);
}